// round 16
// baseline (speedup 1.0000x reference)
#include <cuda_runtime.h>
#include <math.h>

#define NPTS 16384
#define NCELL 24
#define NCELL3 13824
#define INV_CELL 0.1875f            // NCELL / 128
#define CELLSZ 5.3333333f           // 128 / NCELL
#define CAP 8
#define OVF_CAP 256
#define QBLK 128
#define NPAIRS (2 * NCELL3 * 2)     // (set,cell,jhalf) pairs = 55296
#define NMAIN ((NPAIRS * 2) / QBLK) // 864 main blocks
#define NQBLK (NMAIN + 1)           // + 1 overflow-query block

__device__ int    g_ccnt[2][NCELL3];          // raw counts (may exceed CAP)
__device__ float4 g_slots[2][NCELL3 * CAP];   // w = -0.5*||p||^2
__device__ int    g_ovfn[2];
__device__ float4 g_ovf[2][OVF_CAP];
__device__ float  g_acc;
__device__ int    g_done;

// ---- build: bin points into fixed-capacity cells (measured 5.2us) ----
__global__ void build_kernel(const float* __restrict__ A,
                             const float* __restrict__ B) {
    int i = blockIdx.x * blockDim.x + threadIdx.x;   // 0 .. 2*NPTS-1
    int set = i >> 14;
    int idx = i & (NPTS - 1);
    const float* __restrict__ P = set ? B : A;
    float x = P[3 * idx], y = P[3 * idx + 1], z = P[3 * idx + 2];
    int cx = min((int)(x * INV_CELL), NCELL - 1);
    int cy = min((int)(y * INV_CELL), NCELL - 1);
    int cz = min((int)(z * INV_CELL), NCELL - 1);
    int c = (cx * NCELL + cy) * NCELL + cz;
    float4 pt = make_float4(x, y, z, -0.5f * (x * x + y * y + z * z));
    int pos = atomicAdd(&g_ccnt[set][c], 1);
    if (pos < CAP) {
        g_slots[set][c * CAP + pos] = pt;
    } else {
        int o = atomicAdd(&g_ovfn[set], 1);
        if (o < OVF_CAP) g_ovf[set][o] = pt;
    }
}

// ---- rare-path fallback (noinline: keep hot-path registers low) ----
__device__ __noinline__ float nn_expand(float4 q, int qx, int qy, int qz,
                                        int rs, float best) {
    const int* __restrict__ ccnt = g_ccnt[rs];
    const float4* __restrict__ slots = g_slots[rs];
    float d2 = -2.0f * (q.w + best);
    for (int r = 2; r <= NCELL; r++) {
        float rb = (r - 1) * CELLSZ;
        if (d2 <= rb * rb) break;       // all unscanned points strictly farther
        int x0 = max(qx - r, 0), x1 = min(qx + r, NCELL - 1);
        int y0 = max(qy - r, 0), y1 = min(qy + r, NCELL - 1);
        int z0 = max(qz - r, 0), z1 = min(qz + r, NCELL - 1);
        for (int ix = x0; ix <= x1; ix++)
            for (int iy = y0; iy <= y1; iy++)
                for (int iz = z0; iz <= z1; iz++) {
                    int c = (ix * NCELL + iy) * NCELL + iz;
                    int n = min(ccnt[c], CAP);
                    const float4* s = slots + c * CAP;
                    for (int jj = 0; jj < n; jj++) {
                        float4 t = s[jj];
                        float e = fmaf(q.x, t.x,
                                  fmaf(q.y, t.y, fmaf(q.z, t.z, t.w)));
                        best = fmaxf(best, e);
                    }
                }
        d2 = -2.0f * (q.w + best);
    }
    return d2;
}

// ---- query: thread-pair per (set, cell, jhalf); pair splits 27 cells ----
__global__ __launch_bounds__(QBLK) void query_kernel(float* __restrict__ out) {
    __shared__ float red[QBLK / 32];
    __shared__ int s_last;
    int tid = threadIdx.x;
    int bid = blockIdx.x;
    float vsum = 0.0f;

    if (bid < NMAIN) {
        int gtid = bid * QBLK + tid;
        int par = gtid & 1;                 // lane parity within pair
        int pairid = gtid >> 1;
        int jhalf = pairid & 1;
        int u = pairid >> 1;                // 0 .. 2*NCELL3-1
        int set = (u >= NCELL3);
        int cell = u - set * NCELL3;
        int rs = set ^ 1;

        int nq = min(g_ccnt[set][cell], CAP);
        if (jhalf < nq) {                   // at least one query for this pair
            int qx = cell / (NCELL * NCELL);
            int qy = (cell / NCELL) % NCELL;
            int qz = cell % NCELL;
            const int* __restrict__ ccnt = g_ccnt[rs];
            const float4* __restrict__ slots = g_slots[rs];
            int novf = min(g_ovfn[rs], OVF_CAP);
            unsigned pmask = 3u << (tid & 30);   // this pair's shfl mask

            for (int j = jhalf; j < nq; j += 2) {
                float4 q = g_slots[set][cell * CAP + j];
                float best = -1e30f;

                // this thread's half of the 27 neighbor cells (13 or 14)
                for (int k = par; k < 27; k += 2) {
                    int ix = qx + k / 9 - 1;
                    int iy = qy + (k / 3) % 3 - 1;
                    int iz = qz + k % 3 - 1;
                    if ((unsigned)ix < NCELL && (unsigned)iy < NCELL &&
                        (unsigned)iz < NCELL) {
                        int c = (ix * NCELL + iy) * NCELL + iz;
                        int m = min(ccnt[c], CAP);
                        const float4* s = slots + c * CAP;
                        for (int t = 0; t < m; t++) {
                            float4 p = s[t];
                            float e = fmaf(q.x, p.x,
                                      fmaf(q.y, p.y, fmaf(q.z, p.z, p.w)));
                            best = fmaxf(best, e);
                        }
                    }
                }
                // overflow refs, split by parity (expected 0)
                for (int o = par; o < novf; o += 2) {
                    float4 p = g_ovf[rs][o];
                    float e = fmaf(q.x, p.x, fmaf(q.y, p.y, fmaf(q.z, p.z, p.w)));
                    best = fmaxf(best, e);
                }

                // combine pair halves (both lanes converged: same j sequence)
                best = fmaxf(best, __shfl_xor_sync(pmask, best, 1));
                float d2 = -2.0f * (q.w + best);
                if (d2 > CELLSZ * CELLSZ)       // ~0.7%: pair-uniform expand
                    d2 = nn_expand(q, qx, qy, qz, rs, best);
                if (par == 0) vsum += sqrtf(fmaxf(d2, 0.0f));
            }
        }
    } else {
        // overflow points as queries (expected ~0); per-thread full search
        for (int set = 0; set < 2; set++) {
            int rsv = set ^ 1;
            int no = min(g_ovfn[set], OVF_CAP);
            if (tid < no) {
                float4 q = g_ovf[set][tid];
                int qx = min((int)(q.x * INV_CELL), NCELL - 1);
                int qy = min((int)(q.y * INV_CELL), NCELL - 1);
                int qz = min((int)(q.z * INV_CELL), NCELL - 1);
                float best = -1e30f;
                // r=1 box
                for (int k = 0; k < 27; k++) {
                    int ix = qx + k / 9 - 1;
                    int iy = qy + (k / 3) % 3 - 1;
                    int iz = qz + k % 3 - 1;
                    if ((unsigned)ix < NCELL && (unsigned)iy < NCELL &&
                        (unsigned)iz < NCELL) {
                        int c = (ix * NCELL + iy) * NCELL + iz;
                        int m = min(g_ccnt[rsv][c], CAP);
                        for (int t = 0; t < m; t++) {
                            float4 p = g_slots[rsv][c * CAP + t];
                            float e = fmaf(q.x, p.x,
                                      fmaf(q.y, p.y, fmaf(q.z, p.z, p.w)));
                            best = fmaxf(best, e);
                        }
                    }
                }
                int novf = min(g_ovfn[rsv], OVF_CAP);
                for (int o = 0; o < novf; o++) {
                    float4 p = g_ovf[rsv][o];
                    float e = fmaf(q.x, p.x, fmaf(q.y, p.y, fmaf(q.z, p.z, p.w)));
                    best = fmaxf(best, e);
                }
                float d2 = nn_expand(q, qx, qy, qz, rsv, best);
                vsum += sqrtf(fmaxf(d2, 0.0f));
            }
        }
    }

    // ---- block sum -> global atomic; last block writes out + resets ----
    float v = vsum;
    #pragma unroll
    for (int o = 16; o > 0; o >>= 1) v += __shfl_down_sync(0xFFFFFFFFu, v, o);
    int lane = tid & 31, wid = tid >> 5;
    if (lane == 0) red[wid] = v;
    __syncthreads();
    if (tid == 0) {
        float bs = 0.0f;
        #pragma unroll
        for (int w = 0; w < QBLK / 32; w++) bs += red[w];
        atomicAdd(&g_acc, bs);
        __threadfence();
        s_last = (atomicAdd(&g_done, 1) == NQBLK - 1);
    }
    __syncthreads();
    if (s_last) {
        if (tid == 0) {
            out[0] = *((volatile float*)&g_acc) * (1.0f / (2.0f * NPTS));
            g_acc = 0.0f;
            g_done = 0;
            g_ovfn[0] = 0;
            g_ovfn[1] = 0;
        }
        for (int c = tid; c < 2 * NCELL3; c += QBLK)
            ((int*)g_ccnt)[c] = 0;
    }
}

extern "C" void kernel_launch(void* const* d_in, const int* in_sizes, int n_in,
                              void* d_out, int out_size) {
    const float* a = (const float*)d_in[0];
    const float* b = (const float*)d_in[1];
    float* out = (float*)d_out;

    build_kernel<<<(2 * NPTS) / 256, 256>>>(a, b);
    query_kernel<<<NQBLK, QBLK>>>(out);
}

// round 17
// speedup vs baseline: 1.0949x; 1.0949x over previous
#include <cuda_runtime.h>
#include <math.h>

#define NPTS 16384
#define NCELL 24
#define NCELL3 13824
#define INV_CELL 0.1875f            // NCELL / 128
#define CELLSZ 5.3333333f           // 128 / NCELL
#define CAP 8
#define OVF_CAP 256
#define QBLK 256
#define NMAIN ((2 * NCELL3 * 2) / QBLK)   // 216 main blocks (55296 threads)
#define NQBLK (NMAIN + 1)                 // + 1 overflow-query block

__device__ int    g_ccnt[2][NCELL3];          // raw counts (may exceed CAP)
__device__ float4 g_slots[2][NCELL3 * CAP];   // w = -0.5*||p||^2
__device__ int    g_ovfn[2];
__device__ float4 g_ovf[2][OVF_CAP];
__device__ float  g_acc;
__device__ int    g_done;

// ---- build: bin points into fixed-capacity cells (measured 5.2us) ----
__global__ void build_kernel(const float* __restrict__ A,
                             const float* __restrict__ B) {
    int i = blockIdx.x * blockDim.x + threadIdx.x;   // 0 .. 2*NPTS-1
    int set = i >> 14;
    int idx = i & (NPTS - 1);
    const float* __restrict__ P = set ? B : A;
    float x = P[3 * idx], y = P[3 * idx + 1], z = P[3 * idx + 2];
    int cx = min((int)(x * INV_CELL), NCELL - 1);
    int cy = min((int)(y * INV_CELL), NCELL - 1);
    int cz = min((int)(z * INV_CELL), NCELL - 1);
    int c = (cx * NCELL + cy) * NCELL + cz;
    float4 pt = make_float4(x, y, z, -0.5f * (x * x + y * y + z * z));
    int pos = atomicAdd(&g_ccnt[set][c], 1);
    if (pos < CAP) {
        g_slots[set][c * CAP + pos] = pt;
    } else {
        int o = atomicAdd(&g_ovfn[set], 1);
        if (o < OVF_CAP) g_ovf[set][o] = pt;
    }
}

// Plain per-thread NN over slot grid. best seeded from r=1 scan; expands as needed.
__device__ __forceinline__ float nn_query(float4 q, int qx, int qy, int qz,
                                          const int* __restrict__ ccnt,
                                          const float4* __restrict__ slots,
                                          const float4* __restrict__ ovf,
                                          int novf) {
    float bestA = -1e30f, bestB = -1e30f;   // two chains for MLP

    // ---- radius-1: static 3x3x3, dynamic inner; alternate accumulators ----
    #pragma unroll
    for (int dx = -1; dx <= 1; dx++) {
        int ix = qx + dx;
        if ((unsigned)ix >= NCELL) continue;
        #pragma unroll
        for (int dy = -1; dy <= 1; dy++) {
            int iy = qy + dy;
            if ((unsigned)iy >= NCELL) continue;
            int rowc = (ix * NCELL + iy) * NCELL;
            #pragma unroll
            for (int dz = -1; dz <= 1; dz++) {
                int iz = qz + dz;
                if ((unsigned)iz >= NCELL) continue;
                int c = rowc + iz;
                int m = min(ccnt[c], CAP);
                const float4* s = slots + c * CAP;
                if (dz == 0) {
                    for (int t = 0; t < m; t++) {
                        float4 p = s[t];
                        float e = fmaf(q.x, p.x, fmaf(q.y, p.y, fmaf(q.z, p.z, p.w)));
                        bestA = fmaxf(bestA, e);
                    }
                } else {
                    for (int t = 0; t < m; t++) {
                        float4 p = s[t];
                        float e = fmaf(q.x, p.x, fmaf(q.y, p.y, fmaf(q.z, p.z, p.w)));
                        bestB = fmaxf(bestB, e);
                    }
                }
            }
        }
    }
    // overflow refs (expected ~0)
    for (int o = 0; o < novf; o++) {
        float4 p = ovf[o];
        float e = fmaf(q.x, p.x, fmaf(q.y, p.y, fmaf(q.z, p.z, p.w)));
        bestA = fmaxf(bestA, e);
    }
    float best = fmaxf(bestA, bestB);
    float d2 = -2.0f * (q.w + best);

    // ---- rare expansion (~0.7%) ----
    for (int r = 2; r <= NCELL; r++) {
        float rb = (r - 1) * CELLSZ;
        if (d2 <= rb * rb) break;       // all unscanned points strictly farther
        int x0 = max(qx - r, 0), x1 = min(qx + r, NCELL - 1);
        int y0 = max(qy - r, 0), y1 = min(qy + r, NCELL - 1);
        int z0 = max(qz - r, 0), z1 = min(qz + r, NCELL - 1);
        for (int ix = x0; ix <= x1; ix++)
            for (int iy = y0; iy <= y1; iy++) {
                int rowc = (ix * NCELL + iy) * NCELL;
                for (int iz = z0; iz <= z1; iz++) {
                    int c = rowc + iz;
                    int m = min(ccnt[c], CAP);
                    const float4* s = slots + c * CAP;
                    for (int t = 0; t < m; t++) {
                        float4 p = s[t];
                        float e = fmaf(q.x, p.x, fmaf(q.y, p.y, fmaf(q.z, p.z, p.w)));
                        best = fmaxf(best, e);
                    }
                }
            }
        d2 = -2.0f * (q.w + best);
    }
    return d2;
}

// ---- query: thread = (set, cell, j-parity); plain per-thread loops ----
__global__ __launch_bounds__(QBLK) void query_kernel(float* __restrict__ out) {
    __shared__ float red[QBLK / 32];
    __shared__ int s_last;
    int tid = threadIdx.x;
    int bid = blockIdx.x;
    float vsum = 0.0f;

    if (bid < NMAIN) {
        int gtid = bid * QBLK + tid;
        int j0 = gtid & 1;
        int u = gtid >> 1;                  // 0 .. 2*NCELL3-1
        int set = (u >= NCELL3);
        int cell = u - set * NCELL3;
        int rs = set ^ 1;

        int nq = min(g_ccnt[set][cell], CAP);
        if (j0 < nq) {
            int qx = cell / (NCELL * NCELL);
            int qy = (cell / NCELL) % NCELL;
            int qz = cell % NCELL;
            const int* __restrict__ ccnt = g_ccnt[rs];
            const float4* __restrict__ slots = g_slots[rs];
            const float4* __restrict__ ovf = g_ovf[rs];
            int novf = min(g_ovfn[rs], OVF_CAP);

            for (int j = j0; j < nq; j += 2) {
                float4 q = g_slots[set][cell * CAP + j];
                float d2 = nn_query(q, qx, qy, qz, ccnt, slots, ovf, novf);
                vsum += sqrtf(fmaxf(d2, 0.0f));
            }
        }
    } else {
        // overflow points as queries (expected ~0)
        for (int set = 0; set < 2; set++) {
            int rsv = set ^ 1;
            int no = min(g_ovfn[set], OVF_CAP);
            if (tid < no) {
                float4 q = g_ovf[set][tid];
                int qx = min((int)(q.x * INV_CELL), NCELL - 1);
                int qy = min((int)(q.y * INV_CELL), NCELL - 1);
                int qz = min((int)(q.z * INV_CELL), NCELL - 1);
                float d2 = nn_query(q, qx, qy, qz, g_ccnt[rsv], g_slots[rsv],
                                    g_ovf[rsv], min(g_ovfn[rsv], OVF_CAP));
                vsum += sqrtf(fmaxf(d2, 0.0f));
            }
        }
    }

    // ---- block sum -> global atomic; last block writes out + resets ----
    float v = vsum;
    #pragma unroll
    for (int o = 16; o > 0; o >>= 1) v += __shfl_down_sync(0xFFFFFFFFu, v, o);
    int lane = tid & 31, wid = tid >> 5;
    if (lane == 0) red[wid] = v;
    __syncthreads();
    if (tid == 0) {
        float bs = 0.0f;
        #pragma unroll
        for (int w = 0; w < QBLK / 32; w++) bs += red[w];
        atomicAdd(&g_acc, bs);
        __threadfence();
        s_last = (atomicAdd(&g_done, 1) == NQBLK - 1);
    }
    __syncthreads();
    if (s_last) {
        if (tid == 0) {
            out[0] = *((volatile float*)&g_acc) * (1.0f / (2.0f * NPTS));
            g_acc = 0.0f;
            g_done = 0;
            g_ovfn[0] = 0;
            g_ovfn[1] = 0;
        }
        for (int c = tid; c < 2 * NCELL3; c += QBLK)
            ((int*)g_ccnt)[c] = 0;
    }
}

extern "C" void kernel_launch(void* const* d_in, const int* in_sizes, int n_in,
                              void* d_out, int out_size) {
    const float* a = (const float*)d_in[0];
    const float* b = (const float*)d_in[1];
    float* out = (float*)d_out;

    build_kernel<<<(2 * NPTS) / 256, 256>>>(a, b);
    query_kernel<<<NQBLK, QBLK>>>(out);
}